// round 3
// baseline (speedup 1.0000x reference)
#include <cuda_runtime.h>
#include <math.h>

#define BATCH 2
#define SEQ 2048
#define DMODEL 1024
#define NHEADS 16
#define DKH 64
#define MROWS (BATCH*SEQ)          // 4096
#define HALF_DK 32                 // rope pairs per head

// ---------------- scratch (no allocation allowed) ----------------
__device__ __align__(16) float g_Q[BATCH*NHEADS*SEQ*DKH];
__device__ __align__(16) float g_K[BATCH*NHEADS*SEQ*DKH];
__device__ __align__(16) float g_V[BATCH*NHEADS*SEQ*DKH];
__device__ __align__(16) float g_O[BATCH*SEQ*DMODEL];
__device__ float g_cos[SEQ*HALF_DK];
__device__ float g_sin[SEQ*HALF_DK];

// ---------------- RoPE table: replicate reference fp32 angle, then exact sin/cos ----------------
__global__ void rope_table_k() {
    int idx = blockIdx.x * 256 + threadIdx.x;
    if (idx >= SEQ * HALF_DK) return;
    int s = idx >> 5;
    int p = idx & 31;
    // inv_freq = 10000^(-2p/64), rounded to fp32 like the reference
    float invf = (float)pow(10000.0, -(double)p / 32.0);
    float angf = (float)s * invf;          // fp32 multiply, same rounding as reference
    double ang = (double)angf;
    g_cos[idx] = (float)cos(ang);
    g_sin[idx] = (float)sin(ang);
}

// ---------------- GEMM: out[m,n] = sum_k A[m,k] * W[n,k] ----------------
// MODE 0: natural row-major out [M, N]
// MODE 1: headed layout [B,H,S,DK] + RoPE
// MODE 2: headed layout, no RoPE
template<int MODE>
__global__ __launch_bounds__(256, 2) void gemm_k(const float* __restrict__ A,
                                                 const float* __restrict__ W,
                                                 float* __restrict__ out) {
    __shared__ float As[16][132];   // [k][m] transposed
    __shared__ float Ws[16][132];   // [k][n] transposed
    const int tid = threadIdx.x;
    const int ty = tid >> 4, tx = tid & 15;
    const int m0 = blockIdx.y << 7, n0 = blockIdx.x << 7;

    float acc[2][2][4][4];
#pragma unroll
    for (int a = 0; a < 2; a++)
#pragma unroll
        for (int b = 0; b < 2; b++)
#pragma unroll
            for (int i = 0; i < 4; i++)
#pragma unroll
                for (int j = 0; j < 4; j++) acc[a][b][i][j] = 0.f;

    for (int kt = 0; kt < DMODEL; kt += 16) {
#pragma unroll
        for (int c = 0; c < 2; c++) {
            int f = tid + (c << 8);      // 0..511
            int row = f >> 2;            // 0..127
            int kc = (f & 3) << 2;       // 0,4,8,12
            float4 va = *(const float4*)(A + (size_t)(m0 + row) * DMODEL + kt + kc);
            As[kc + 0][row] = va.x; As[kc + 1][row] = va.y;
            As[kc + 2][row] = va.z; As[kc + 3][row] = va.w;
            float4 vb = *(const float4*)(W + (size_t)(n0 + row) * DMODEL + kt + kc);
            Ws[kc + 0][row] = vb.x; Ws[kc + 1][row] = vb.y;
            Ws[kc + 2][row] = vb.z; Ws[kc + 3][row] = vb.w;
        }
        __syncthreads();
#pragma unroll
        for (int kk = 0; kk < 16; kk++) {
            float a[2][4], bb[2][4];
            *(float4*)a[0]  = *(const float4*)&As[kk][(ty << 2)];
            *(float4*)a[1]  = *(const float4*)&As[kk][64 + (ty << 2)];
            *(float4*)bb[0] = *(const float4*)&Ws[kk][(tx << 2)];
            *(float4*)bb[1] = *(const float4*)&Ws[kk][64 + (tx << 2)];
#pragma unroll
            for (int rg = 0; rg < 2; rg++)
#pragma unroll
                for (int cg = 0; cg < 2; cg++)
#pragma unroll
                    for (int i = 0; i < 4; i++)
#pragma unroll
                        for (int j = 0; j < 4; j++)
                            acc[rg][cg][i][j] += a[rg][i] * bb[cg][j];
        }
        __syncthreads();
    }

    // epilogue
#pragma unroll
    for (int rg = 0; rg < 2; rg++)
#pragma unroll
        for (int i = 0; i < 4; i++) {
            int m = m0 + (rg << 6) + (ty << 2) + i;
            int b = m >> 11;
            int s = m & (SEQ - 1);
#pragma unroll
            for (int cg = 0; cg < 2; cg++) {
                float v0 = acc[rg][cg][i][0], v1 = acc[rg][cg][i][1];
                float v2 = acc[rg][cg][i][2], v3 = acc[rg][cg][i][3];
                int nb = n0 + (cg << 6) + (tx << 2);
                if (MODE == 1) {
                    int p0 = (tx << 1);
                    float c0 = g_cos[(s << 5) + p0],     s0 = g_sin[(s << 5) + p0];
                    float c1 = g_cos[(s << 5) + p0 + 1], s1 = g_sin[(s << 5) + p0 + 1];
                    float e0 = v0 * c0 - v1 * s0, o0 = v0 * s0 + v1 * c0;
                    float e1 = v2 * c1 - v3 * s1, o1 = v2 * s1 + v3 * c1;
                    v0 = e0; v1 = o0; v2 = e1; v3 = o1;
                }
                if (MODE == 0) {
                    *(float4*)(out + (size_t)m * DMODEL + nb) = make_float4(v0, v1, v2, v3);
                } else {
                    int h = nb >> 6;
                    int dk = nb & 63;
                    *(float4*)(out + (((size_t)(b * NHEADS + h) * SEQ + s) << 6) + dk) =
                        make_float4(v0, v1, v2, v3);
                }
            }
        }
}

// ---------------- Causal flash attention, fp32 ----------------
// grid: (S/64, B*H), 256 threads, 4x4 per thread.
__global__ __launch_bounds__(256, 3) void flash_k(const float* __restrict__ Q,
                                                  const float* __restrict__ K,
                                                  const float* __restrict__ V,
                                                  float* __restrict__ O) {
    extern __shared__ float sm[];
    float* Qt = sm;                 // [64 d][68] transposed
    float* Kt = sm + 64 * 68;       // [64 d][68] transposed
    float* Vs = sm + 2 * 64 * 68;   // [64 j][68] natural
    float* Ps = sm + 3 * 64 * 68;   // [64 r][68] natural

    const int tid = threadIdx.x, ty = tid >> 4, tx = tid & 15;
    const int bq = blockIdx.x, bh = blockIdx.y;
    const float* Qg = Q + ((size_t)bh * SEQ + (bq << 6)) * DKH;
    const float* Kg = K + (size_t)bh * SEQ * DKH;
    const float* Vg = V + (size_t)bh * SEQ * DKH;

    // load Q tile transposed
#pragma unroll
    for (int c = 0; c < 4; c++) {
        int f = tid + (c << 8);
        int row = f >> 4, c4 = (f & 15) << 2;
        float4 q = *(const float4*)(Qg + row * DKH + c4);
        Qt[(c4 + 0) * 68 + row] = q.x; Qt[(c4 + 1) * 68 + row] = q.y;
        Qt[(c4 + 2) * 68 + row] = q.z; Qt[(c4 + 3) * 68 + row] = q.w;
    }

    float acc[4][4];
    float mr[4], lr[4];
#pragma unroll
    for (int i = 0; i < 4; i++) {
        mr[i] = -1e30f; lr[i] = 0.f;
#pragma unroll
        for (int j = 0; j < 4; j++) acc[i][j] = 0.f;
    }

    for (int kt = 0; kt <= bq; kt++) {
        __syncthreads();   // previous PV done before overwriting K/V
#pragma unroll
        for (int c = 0; c < 4; c++) {
            int f = tid + (c << 8);
            int row = f >> 4, c4 = (f & 15) << 2;
            float4 kv = *(const float4*)(Kg + ((size_t)(kt << 6) + row) * DKH + c4);
            Kt[(c4 + 0) * 68 + row] = kv.x; Kt[(c4 + 1) * 68 + row] = kv.y;
            Kt[(c4 + 2) * 68 + row] = kv.z; Kt[(c4 + 3) * 68 + row] = kv.w;
            float4 vv = *(const float4*)(Vg + ((size_t)(kt << 6) + row) * DKH + c4);
            *(float4*)&Vs[row * 68 + c4] = vv;
        }
        __syncthreads();

        float sc[4][4];
#pragma unroll
        for (int i = 0; i < 4; i++)
#pragma unroll
            for (int j = 0; j < 4; j++) sc[i][j] = 0.f;

#pragma unroll 8
        for (int dd = 0; dd < 64; dd++) {
            float4 a = *(const float4*)&Qt[dd * 68 + (ty << 2)];
            float4 b = *(const float4*)&Kt[dd * 68 + (tx << 2)];
            float av[4] = {a.x, a.y, a.z, a.w};
            float bv[4] = {b.x, b.y, b.z, b.w};
#pragma unroll
            for (int i = 0; i < 4; i++)
#pragma unroll
                for (int j = 0; j < 4; j++) sc[i][j] += av[i] * bv[j];
        }

        const bool diag = (kt == bq);
#pragma unroll
        for (int i = 0; i < 4; i++)
#pragma unroll
            for (int j = 0; j < 4; j++) {
                sc[i][j] *= 0.125f;
                if (diag && ((tx << 2) + j > (ty << 2) + i)) sc[i][j] = -1e30f;
            }

#pragma unroll
        for (int i = 0; i < 4; i++) {
            float mx = fmaxf(fmaxf(sc[i][0], sc[i][1]), fmaxf(sc[i][2], sc[i][3]));
#pragma unroll
            for (int off = 8; off; off >>= 1)
                mx = fmaxf(mx, __shfl_xor_sync(0xffffffffu, mx, off));
            float mnew = fmaxf(mr[i], mx);
            float corr = __expf(mr[i] - mnew);
            mr[i] = mnew;
            float rs = 0.f;
#pragma unroll
            for (int j = 0; j < 4; j++) {
                float p = __expf(sc[i][j] - mnew);
                sc[i][j] = p;
                rs += p;
            }
#pragma unroll
            for (int off = 8; off; off >>= 1)
                rs += __shfl_xor_sync(0xffffffffu, rs, off);
            lr[i] = lr[i] * corr + rs;
#pragma unroll
            for (int j = 0; j < 4; j++) acc[i][j] *= corr;
        }

#pragma unroll
        for (int i = 0; i < 4; i++)
            *(float4*)&Ps[((ty << 2) + i) * 68 + (tx << 2)] =
                make_float4(sc[i][0], sc[i][1], sc[i][2], sc[i][3]);
        __syncthreads();

#pragma unroll 8
        for (int jj = 0; jj < 64; jj++) {
            float4 b = *(const float4*)&Vs[jj * 68 + (tx << 2)];
            float bv[4] = {b.x, b.y, b.z, b.w};
            float a0 = Ps[((ty << 2) + 0) * 68 + jj];
            float a1 = Ps[((ty << 2) + 1) * 68 + jj];
            float a2 = Ps[((ty << 2) + 2) * 68 + jj];
            float a3 = Ps[((ty << 2) + 3) * 68 + jj];
#pragma unroll
            for (int j = 0; j < 4; j++) {
                acc[0][j] += a0 * bv[j];
                acc[1][j] += a1 * bv[j];
                acc[2][j] += a2 * bv[j];
                acc[3][j] += a3 * bv[j];
            }
        }
    }

    const int b = bh >> 4, h = bh & 15;
#pragma unroll
    for (int i = 0; i < 4; i++) {
        int s = (bq << 6) + (ty << 2) + i;
        float inv = 1.0f / lr[i];
        *(float4*)&O[((size_t)(b * SEQ + s)) * DMODEL + (h << 6) + (tx << 2)] =
            make_float4(acc[i][0] * inv, acc[i][1] * inv, acc[i][2] * inv, acc[i][3] * inv);
    }
}

// ---------------- launch ----------------
extern "C" void kernel_launch(void* const* d_in, const int* in_sizes, int n_in,
                              void* d_out, int out_size) {
    const float* x  = (const float*)d_in[0];
    // d_in[1] = token_positions = arange(SEQ); position == row index, used implicitly
    const float* Wq = (const float*)d_in[2];
    const float* Wk = (const float*)d_in[3];
    const float* Wv = (const float*)d_in[4];
    const float* Wo = (const float*)d_in[5];
    float* out = (float*)d_out;

    float *q, *k, *v, *o;
    cudaGetSymbolAddress((void**)&q, g_Q);
    cudaGetSymbolAddress((void**)&k, g_K);
    cudaGetSymbolAddress((void**)&v, g_V);
    cudaGetSymbolAddress((void**)&o, g_O);

    const int smem = 4 * 64 * 68 * (int)sizeof(float);  // 69632
    cudaFuncSetAttribute(flash_k, cudaFuncAttributeMaxDynamicSharedMemorySize, smem);

    rope_table_k<<<(SEQ * HALF_DK + 255) / 256, 256>>>();

    dim3 gg(DMODEL / 128, MROWS / 128);
    gemm_k<1><<<gg, 256>>>(x, Wq, q);
    gemm_k<1><<<gg, 256>>>(x, Wk, k);
    gemm_k<2><<<gg, 256>>>(x, Wv, v);

    flash_k<<<dim3(SEQ / 64, BATCH * NHEADS), 256, smem>>>(q, k, v, o);

    gemm_k<0><<<gg, 256>>>(o, Wo, out);
}

// round 5
// speedup vs baseline: 1.3707x; 1.3707x over previous
#include <cuda_runtime.h>
#include <cuda_bf16.h>
#include <stdint.h>
#include <math.h>

#define BATCH 2
#define SEQ 2048
#define DMODEL 1024
#define NHEADS 16
#define DKH 64
#define MROWS (BATCH*SEQ)          // 4096
#define HALF_DK 32
#define K3 (3*DMODEL)              // 3072 split-K

// ---------------- scratch (no allocation allowed) ----------------
__device__ __align__(16) float g_Q[BATCH*NHEADS*SEQ*DKH];
__device__ __align__(16) float g_K[BATCH*NHEADS*SEQ*DKH];
__device__ __align__(16) float g_V[BATCH*NHEADS*SEQ*DKH];
__device__ __align__(16) float g_O[BATCH*SEQ*DMODEL];
__device__ __align__(16) __nv_bfloat16 g_Xc[MROWS*K3];      // split activations (reused for O)
__device__ __align__(16) __nv_bfloat16 g_Wc[DMODEL*K3];     // split weights (reused)
__device__ float g_cos[SEQ*HALF_DK];
__device__ float g_sin[SEQ*HALF_DK];

// ---------------- RoPE table ----------------
__global__ void rope_table_k() {
    int idx = blockIdx.x * 256 + threadIdx.x;
    if (idx >= SEQ * HALF_DK) return;
    int s = idx >> 5;
    int p = idx & 31;
    float invf = (float)pow(10000.0, -(double)p / 32.0);
    float angf = (float)s * invf;
    double ang = (double)angf;
    g_cos[idx] = (float)cos(ang);
    g_sin[idx] = (float)sin(ang);
}

// ---------------- hi/lo split conversion ----------------
// WMODE 0 (activations): segments [hi | hi | lo]
// WMODE 1 (weights):     segments [hi | lo | hi]
template<int WMODE>
__global__ void conv_split_k(const float* __restrict__ src, __nv_bfloat16* __restrict__ dst, int nelem) {
    int idx = blockIdx.x * 256 + threadIdx.x;
    int i4 = idx << 2;
    if (i4 >= nelem) return;
    float4 v = *(const float4*)(src + i4);
    __nv_bfloat16 h0 = __float2bfloat16(v.x), h1 = __float2bfloat16(v.y);
    __nv_bfloat16 h2 = __float2bfloat16(v.z), h3 = __float2bfloat16(v.w);
    __nv_bfloat16 l0 = __float2bfloat16(v.x - __bfloat162float(h0));
    __nv_bfloat16 l1 = __float2bfloat16(v.y - __bfloat162float(h1));
    __nv_bfloat16 l2 = __float2bfloat16(v.z - __bfloat162float(h2));
    __nv_bfloat16 l3 = __float2bfloat16(v.w - __bfloat162float(h3));
    int row = i4 >> 10, col = i4 & 1023;
    __nv_bfloat16* p = dst + (size_t)row * K3 + col;
    __nv_bfloat162 H01; H01.x = h0; H01.y = h1;
    __nv_bfloat162 H23; H23.x = h2; H23.y = h3;
    __nv_bfloat162 L01; L01.x = l0; L01.y = l1;
    __nv_bfloat162 L23; L23.x = l2; L23.y = l3;
    *(__nv_bfloat162*)(p)     = H01;
    *(__nv_bfloat162*)(p + 2) = H23;
    if (WMODE == 0) {
        *(__nv_bfloat162*)(p + 1024) = H01;
        *(__nv_bfloat162*)(p + 1026) = H23;
        *(__nv_bfloat162*)(p + 2048) = L01;
        *(__nv_bfloat162*)(p + 2050) = L23;
    } else {
        *(__nv_bfloat162*)(p + 1024) = L01;
        *(__nv_bfloat162*)(p + 1026) = L23;
        *(__nv_bfloat162*)(p + 2048) = H01;
        *(__nv_bfloat162*)(p + 2050) = H23;
    }
}

// ---------------- bf16 tensor-core GEMM ----------------
// out[m,n] = sum_k A'[m,k]*B'[n,k], K=3072. BM=BN=128, BK=32, 3-stage cp.async.
// MODE 0: natural [M,N]; MODE 1: headed + RoPE; MODE 2: headed.
#define SROW 56                     // bf16 elems per smem row (112B)
#define STAGE_BYTES (128*SROW*2)    // 14336
#define NKSTAGES 96                 // 3072/32

__device__ __forceinline__ void ldsm4(uint32_t& r0, uint32_t& r1, uint32_t& r2, uint32_t& r3, uint32_t addr) {
    asm volatile("ldmatrix.sync.aligned.m8n8.x4.shared.b16 {%0,%1,%2,%3},[%4];"
                 : "=r"(r0), "=r"(r1), "=r"(r2), "=r"(r3) : "r"(addr));
}
__device__ __forceinline__ void mma_bf16(float* d, const uint32_t* a, uint32_t b0, uint32_t b1) {
    asm volatile("mma.sync.aligned.m16n8k16.row.col.f32.bf16.bf16.f32 "
                 "{%0,%1,%2,%3},{%4,%5,%6,%7},{%8,%9},{%0,%1,%2,%3};"
                 : "+f"(d[0]), "+f"(d[1]), "+f"(d[2]), "+f"(d[3])
                 : "r"(a[0]), "r"(a[1]), "r"(a[2]), "r"(a[3]), "r"(b0), "r"(b1));
}
__device__ __forceinline__ void cpasync16(uint32_t dst, const void* src) {
    asm volatile("cp.async.cg.shared.global [%0],[%1],16;" :: "r"(dst), "l"(src));
}

template<int MODE>
__global__ __launch_bounds__(256, 2) void gemm_bf16_k(const __nv_bfloat16* __restrict__ A,
                                                      const __nv_bfloat16* __restrict__ B,
                                                      float* __restrict__ out) {
    extern __shared__ char smem[];
    const uint32_t sbase = (uint32_t)__cvta_generic_to_shared(smem);
    const uint32_t sA = sbase;
    const uint32_t sB = sbase + 3 * STAGE_BYTES;

    const int tid = threadIdx.x, lane = tid & 31, wid = tid >> 5;
    const int warp_m = wid & 1, warp_n = wid >> 1;
    const int m0 = blockIdx.y << 7, n0 = blockIdx.x << 7;

    // global load mapping: 4 threads per row (16B each), 64 rows per 256 threads
    const int rowL = tid >> 2, kc = tid & 3;
    const __nv_bfloat16* gA1 = A + (size_t)(m0 + rowL) * K3 + kc * 8;
    const __nv_bfloat16* gA2 = A + (size_t)(m0 + rowL + 64) * K3 + kc * 8;
    const __nv_bfloat16* gB1 = B + (size_t)(n0 + rowL) * K3 + kc * 8;
    const __nv_bfloat16* gB2 = B + (size_t)(n0 + rowL + 64) * K3 + kc * 8;
    const uint32_t dA1 = (uint32_t)(rowL * SROW + kc * 8) * 2u;
    const uint32_t dA2 = (uint32_t)((rowL + 64) * SROW + kc * 8) * 2u;

    // ldmatrix lane offsets (bf16 elems)
    const int arow = (lane & 7) + 8 * ((lane >> 3) & 1);
    const int ak8  = (lane >> 4) * 8;
    const int brow = (lane & 7) + 8 * (lane >> 4);
    const int bk8  = ((lane >> 3) & 1) * 8;
    const uint32_t aoff = (uint32_t)((warp_m * 64 + arow) * SROW + ak8) * 2u;
    const uint32_t boff = (uint32_t)((warp_n * 32 + brow) * SROW + bk8) * 2u;

    float acc[4][4][4];
#pragma unroll
    for (int mi = 0; mi < 4; mi++)
#pragma unroll
        for (int ni = 0; ni < 4; ni++)
#pragma unroll
            for (int r = 0; r < 4; r++) acc[mi][ni][r] = 0.f;

#define ISSUE_STAGE(st) do { int bf_ = (st) % 3; \
    cpasync16(sA + bf_ * STAGE_BYTES + dA1, gA1 + (st) * 32); \
    cpasync16(sA + bf_ * STAGE_BYTES + dA2, gA2 + (st) * 32); \
    cpasync16(sB + bf_ * STAGE_BYTES + dA1, gB1 + (st) * 32); \
    cpasync16(sB + bf_ * STAGE_BYTES + dA2, gB2 + (st) * 32); \
    asm volatile("cp.async.commit_group;"); } while (0)

    ISSUE_STAGE(0);
    ISSUE_STAGE(1);

    for (int s = 0; s < NKSTAGES; s++) {
        if (s < NKSTAGES - 1) asm volatile("cp.async.wait_group 1;" ::: "memory");
        else                  asm volatile("cp.async.wait_group 0;" ::: "memory");
        __syncthreads();
        if (s + 2 < NKSTAGES) ISSUE_STAGE(s + 2);

        const int bf = s % 3;
        const uint32_t aSt = sA + bf * STAGE_BYTES + aoff;
        const uint32_t bSt = sB + bf * STAGE_BYTES + boff;
#pragma unroll
        for (int ks = 0; ks < 2; ks++) {
            uint32_t a[4][4], b[2][4];
#pragma unroll
            for (int mi = 0; mi < 4; mi++)
                ldsm4(a[mi][0], a[mi][1], a[mi][2], a[mi][3],
                      aSt + (uint32_t)(mi * 16 * SROW + ks * 16) * 2u);
#pragma unroll
            for (int np = 0; np < 2; np++)
                ldsm4(b[np][0], b[np][1], b[np][2], b[np][3],
                      bSt + (uint32_t)(np * 16 * SROW + ks * 16) * 2u);
#pragma unroll
            for (int mi = 0; mi < 4; mi++)
#pragma unroll
                for (int ni = 0; ni < 4; ni++)
                    mma_bf16(acc[mi][ni], a[mi],
                             b[ni >> 1][(ni & 1) * 2], b[ni >> 1][(ni & 1) * 2 + 1]);
        }
        __syncthreads();
    }
#undef ISSUE_STAGE

    // epilogue
    const int er = m0 + warp_m * 64 + (lane >> 2);
    const int ec = n0 + warp_n * 32 + (lane & 3) * 2;
#pragma unroll
    for (int mi = 0; mi < 4; mi++) {
#pragma unroll
        for (int half = 0; half < 2; half++) {
            int r = er + mi * 16 + half * 8;
            int b = r >> 11, sp = r & (SEQ - 1);
#pragma unroll
            for (int ni = 0; ni < 4; ni++) {
                float v0 = acc[mi][ni][half * 2], v1 = acc[mi][ni][half * 2 + 1];
                int n = ec + ni * 8;
                if (MODE == 0) {
                    *(float2*)(out + (size_t)r * DMODEL + n) = make_float2(v0, v1);
                } else {
                    int h = n >> 6, dk = n & 63;
                    if (MODE == 1) {
                        int p = dk >> 1;
                        float c = g_cos[(sp << 5) + p], sn = g_sin[(sp << 5) + p];
                        float e = v0 * c - v1 * sn, o = v0 * sn + v1 * c;
                        v0 = e; v1 = o;
                    }
                    *(float2*)(out + (((size_t)(b * NHEADS + h) * SEQ + sp) << 6) + dk) =
                        make_float2(v0, v1);
                }
            }
        }
    }
}

// ---------------- Causal flash attention, fp32 (unchanged) ----------------
__global__ __launch_bounds__(256, 3) void flash_k(const float* __restrict__ Q,
                                                  const float* __restrict__ K,
                                                  const float* __restrict__ V,
                                                  float* __restrict__ O) {
    extern __shared__ float smf[];
    float* Qt = smf;
    float* Kt = smf + 64 * 68;
    float* Vs = smf + 2 * 64 * 68;
    float* Ps = smf + 3 * 64 * 68;

    const int tid = threadIdx.x, ty = tid >> 4, tx = tid & 15;
    const int bq = blockIdx.x, bh = blockIdx.y;
    const float* Qg = Q + ((size_t)bh * SEQ + (bq << 6)) * DKH;
    const float* Kg = K + (size_t)bh * SEQ * DKH;
    const float* Vg = V + (size_t)bh * SEQ * DKH;

#pragma unroll
    for (int c = 0; c < 4; c++) {
        int f = tid + (c << 8);
        int row = f >> 4, c4 = (f & 15) << 2;
        float4 q = *(const float4*)(Qg + row * DKH + c4);
        Qt[(c4 + 0) * 68 + row] = q.x; Qt[(c4 + 1) * 68 + row] = q.y;
        Qt[(c4 + 2) * 68 + row] = q.z; Qt[(c4 + 3) * 68 + row] = q.w;
    }

    float acc[4][4];
    float mr[4], lr[4];
#pragma unroll
    for (int i = 0; i < 4; i++) {
        mr[i] = -1e30f; lr[i] = 0.f;
#pragma unroll
        for (int j = 0; j < 4; j++) acc[i][j] = 0.f;
    }

    for (int kt = 0; kt <= bq; kt++) {
        __syncthreads();
#pragma unroll
        for (int c = 0; c < 4; c++) {
            int f = tid + (c << 8);
            int row = f >> 4, c4 = (f & 15) << 2;
            float4 kv = *(const float4*)(Kg + ((size_t)(kt << 6) + row) * DKH + c4);
            Kt[(c4 + 0) * 68 + row] = kv.x; Kt[(c4 + 1) * 68 + row] = kv.y;
            Kt[(c4 + 2) * 68 + row] = kv.z; Kt[(c4 + 3) * 68 + row] = kv.w;
            float4 vv = *(const float4*)(Vg + ((size_t)(kt << 6) + row) * DKH + c4);
            *(float4*)&Vs[row * 68 + c4] = vv;
        }
        __syncthreads();

        float sc[4][4];
#pragma unroll
        for (int i = 0; i < 4; i++)
#pragma unroll
            for (int j = 0; j < 4; j++) sc[i][j] = 0.f;

#pragma unroll 8
        for (int dd = 0; dd < 64; dd++) {
            float4 a = *(const float4*)&Qt[dd * 68 + (ty << 2)];
            float4 b = *(const float4*)&Kt[dd * 68 + (tx << 2)];
            float av[4] = {a.x, a.y, a.z, a.w};
            float bv[4] = {b.x, b.y, b.z, b.w};
#pragma unroll
            for (int i = 0; i < 4; i++)
#pragma unroll
                for (int j = 0; j < 4; j++) sc[i][j] += av[i] * bv[j];
        }

        const bool diag = (kt == bq);
#pragma unroll
        for (int i = 0; i < 4; i++)
#pragma unroll
            for (int j = 0; j < 4; j++) {
                sc[i][j] *= 0.125f;
                if (diag && ((tx << 2) + j > (ty << 2) + i)) sc[i][j] = -1e30f;
            }

#pragma unroll
        for (int i = 0; i < 4; i++) {
            float mx = fmaxf(fmaxf(sc[i][0], sc[i][1]), fmaxf(sc[i][2], sc[i][3]));
#pragma unroll
            for (int off = 8; off; off >>= 1)
                mx = fmaxf(mx, __shfl_xor_sync(0xffffffffu, mx, off));
            float mnew = fmaxf(mr[i], mx);
            float corr = __expf(mr[i] - mnew);
            mr[i] = mnew;
            float rs = 0.f;
#pragma unroll
            for (int j = 0; j < 4; j++) {
                float p = __expf(sc[i][j] - mnew);
                sc[i][j] = p;
                rs += p;
            }
#pragma unroll
            for (int off = 8; off; off >>= 1)
                rs += __shfl_xor_sync(0xffffffffu, rs, off);
            lr[i] = lr[i] * corr + rs;
#pragma unroll
            for (int j = 0; j < 4; j++) acc[i][j] *= corr;
        }

#pragma unroll
        for (int i = 0; i < 4; i++)
            *(float4*)&Ps[((ty << 2) + i) * 68 + (tx << 2)] =
                make_float4(sc[i][0], sc[i][1], sc[i][2], sc[i][3]);
        __syncthreads();

#pragma unroll 8
        for (int jj = 0; jj < 64; jj++) {
            float4 b = *(const float4*)&Vs[jj * 68 + (tx << 2)];
            float bv[4] = {b.x, b.y, b.z, b.w};
            float a0 = Ps[((ty << 2) + 0) * 68 + jj];
            float a1 = Ps[((ty << 2) + 1) * 68 + jj];
            float a2 = Ps[((ty << 2) + 2) * 68 + jj];
            float a3 = Ps[((ty << 2) + 3) * 68 + jj];
#pragma unroll
            for (int j = 0; j < 4; j++) {
                acc[0][j] += a0 * bv[j];
                acc[1][j] += a1 * bv[j];
                acc[2][j] += a2 * bv[j];
                acc[3][j] += a3 * bv[j];
            }
        }
    }

    const int b = bh >> 4, h = bh & 15;
#pragma unroll
    for (int i = 0; i < 4; i++) {
        int s = (bq << 6) + (ty << 2) + i;
        float inv = 1.0f / lr[i];
        *(float4*)&O[((size_t)(b * SEQ + s)) * DMODEL + (h << 6) + (tx << 2)] =
            make_float4(acc[i][0] * inv, acc[i][1] * inv, acc[i][2] * inv, acc[i][3] * inv);
    }
}

// ---------------- launch ----------------
extern "C" void kernel_launch(void* const* d_in, const int* in_sizes, int n_in,
                              void* d_out, int out_size) {
    const float* x  = (const float*)d_in[0];
    const float* Wq = (const float*)d_in[2];
    const float* Wk = (const float*)d_in[3];
    const float* Wv = (const float*)d_in[4];
    const float* Wo = (const float*)d_in[5];
    float* out = (float*)d_out;

    float *q, *k, *v, *o;
    __nv_bfloat16 *xc, *wc;
    cudaGetSymbolAddress((void**)&q, g_Q);
    cudaGetSymbolAddress((void**)&k, g_K);
    cudaGetSymbolAddress((void**)&v, g_V);
    cudaGetSymbolAddress((void**)&o, g_O);
    cudaGetSymbolAddress((void**)&xc, g_Xc);
    cudaGetSymbolAddress((void**)&wc, g_Wc);

    const int gsmem = 6 * STAGE_BYTES;  // 86016
    cudaFuncSetAttribute(gemm_bf16_k<0>, cudaFuncAttributeMaxDynamicSharedMemorySize, gsmem);
    cudaFuncSetAttribute(gemm_bf16_k<1>, cudaFuncAttributeMaxDynamicSharedMemorySize, gsmem);
    cudaFuncSetAttribute(gemm_bf16_k<2>, cudaFuncAttributeMaxDynamicSharedMemorySize, gsmem);
    const int fsmem = 4 * 64 * 68 * (int)sizeof(float);
    cudaFuncSetAttribute(flash_k, cudaFuncAttributeMaxDynamicSharedMemorySize, fsmem);

    rope_table_k<<<(SEQ * HALF_DK + 255) / 256, 256>>>();

    dim3 gg(DMODEL / 128, MROWS / 128);
    const int xblocks = (MROWS * DMODEL / 4 + 255) / 256;
    const int wblocks = (DMODEL * DMODEL / 4 + 255) / 256;

    conv_split_k<0><<<xblocks, 256>>>(x, xc, MROWS * DMODEL);

    conv_split_k<1><<<wblocks, 256>>>(Wq, wc, DMODEL * DMODEL);
    gemm_bf16_k<1><<<gg, 256, gsmem>>>(xc, wc, q);
    conv_split_k<1><<<wblocks, 256>>>(Wk, wc, DMODEL * DMODEL);
    gemm_bf16_k<1><<<gg, 256, gsmem>>>(xc, wc, k);
    conv_split_k<1><<<wblocks, 256>>>(Wv, wc, DMODEL * DMODEL);
    gemm_bf16_k<2><<<gg, 256, gsmem>>>(xc, wc, v);

    flash_k<<<dim3(SEQ / 64, BATCH * NHEADS), 256, fsmem>>>(q, k, v, o);

    conv_split_k<0><<<xblocks, 256>>>(o, xc, MROWS * DMODEL);
    conv_split_k<1><<<wblocks, 256>>>(Wo, wc, DMODEL * DMODEL);
    gemm_bf16_k<0><<<gg, 256, gsmem>>>(xc, wc, out);
}